// round 8
// baseline (speedup 1.0000x reference)
#include <cuda_runtime.h>
#include <cuda_fp16.h>
#include <cstdint>

#define BBATCH 2
#define HH 64
#define WW 64
#define CC 192
#define NH 6
#define HD 32
#define KW 7
#define RR 13
#define NPIX (BBATCH*HH*WW)

// scratch (device globals: allocation-free)
__device__ float g_qkv[(size_t)NPIX * 3 * CC];   // qkv activations (fp32, q pre-scaled)
__device__ float g_att[(size_t)NPIX * CC];       // attention output (tf32-rounded)
__device__ float g_xr [(size_t)NPIX * CC];       // x, tf32-rounded
__device__ float g_wqr[(size_t)3 * CC * CC];     // w_qkv, tf32-rounded
__device__ float g_wpr[(size_t)CC * CC];         // w_proj, tf32-rounded

__device__ __forceinline__ uint32_t f2tf32(float x) {
    uint32_t r;
    asm("cvt.rna.tf32.f32 %0, %1;" : "=r"(r) : "f"(x));
    return r;
}

__device__ __forceinline__ uint32_t smem_u32(const void* p) {
    uint32_t a;
    asm("{ .reg .u64 t; cvta.to.shared.u64 t, %1; cvt.u32.u64 %0, t; }"
        : "=r"(a) : "l"(p));
    return a;
}

__device__ __forceinline__ void cp16(uint32_t dst, const void* src) {
    asm volatile("cp.async.cg.shared.global [%0], [%1], 16;"
                 :: "r"(dst), "l"(src));
}
#define CP_COMMIT() asm volatile("cp.async.commit_group;" ::: "memory")
#define CP_WAIT(N)  asm volatile("cp.async.wait_group %0;" :: "n"(N) : "memory")

__device__ __forceinline__ void mma_tf32(float c[4], const uint32_t a[4],
                                         const uint32_t b[2]) {
    asm volatile(
        "mma.sync.aligned.m16n8k8.row.col.f32.tf32.tf32.f32 "
        "{%0,%1,%2,%3}, {%4,%5,%6,%7}, {%8,%9}, {%0,%1,%2,%3};"
        : "+f"(c[0]), "+f"(c[1]), "+f"(c[2]), "+f"(c[3])
        : "r"(a[0]), "r"(a[1]), "r"(a[2]), "r"(a[3]), "r"(b[0]), "r"(b[1]));
}

// ---------------------------------------------------------------------------
// Pre-pass: round three fp32 arrays to tf32-representable fp32.
// ---------------------------------------------------------------------------
#define N4X ((NPIX * CC) / 4)
#define N4Q ((3 * CC * CC) / 4)
#define N4P ((CC * CC) / 4)
#define N4TOT (N4X + N4Q + N4P)

__global__ __launch_bounds__(256)
void round_pass(const float* __restrict__ x, const float* __restrict__ wq,
                const float* __restrict__ wp)
{
    const int idx = blockIdx.x * 256 + threadIdx.x;
    if (idx >= N4TOT) return;
    const float4* src;
    float4* dst;
    int off;
    if (idx < N4X)            { src = (const float4*)x;  dst = (float4*)g_xr;  off = idx; }
    else if (idx < N4X + N4Q) { src = (const float4*)wq; dst = (float4*)g_wqr; off = idx - N4X; }
    else                      { src = (const float4*)wp; dst = (float4*)g_wpr; off = idx - N4X - N4Q; }
    const float4 v = src[off];
    float4 o;
    o.x = __uint_as_float(f2tf32(v.x));
    o.y = __uint_as_float(f2tf32(v.y));
    o.z = __uint_as_float(f2tf32(v.z));
    o.w = __uint_as_float(f2tf32(v.w));
    dst[off] = o;
}

// ---------------------------------------------------------------------------
// Tensor-core GEMM via mma.sync tf32, cp.async double-buffered, BN=192.
// C[M,N] = A[M,192] * W[N,192]^T, NT, inputs pre-rounded to tf32.
// Warps: (BM/32) x 4; warp tile 32 x 48 (2 x 6 m16n8k8, 12 independent chains).
// QKV: BM=128, 512 thr, grid (3,64). Proj: BM=64, 256 thr, grid (1,128).
// Dynamic smem: (BM + 192) * 32 words * 2 buffers, XOR-16B swizzled.
// ---------------------------------------------------------------------------
#define GBN 192
#define GBK 32
#define GKD 192
#define NCHUNK (GKD / GBK)

template<int BM, int THREADS>
__global__ void __launch_bounds__(THREADS, (BM == 64) ? 2 : 1)
gemm_mma(const float* __restrict__ A, const float* __restrict__ W,
         float* __restrict__ C, int Ncols, int scaleQ)
{
    constexpr int AU = BM * 8 / THREADS;     // A 16B-units per thread
    constexpr int BU = GBN * 8 / THREADS;    // B 16B-units per thread

    extern __shared__ uint32_t smw[];
    uint32_t* Asb = smw;                     // [2][BM][32]
    uint32_t* Bsb = smw + 2 * BM * GBK;      // [2][192][32]

    const int t    = threadIdx.x;
    const int wid  = t >> 5, lane = t & 31;
    const int g    = lane >> 2, q4 = lane & 3;
    const int wM   = wid >> 2, wN = wid & 3;
    const int bm   = blockIdx.y * BM;
    const int bn   = blockIdx.x * GBN;

    uint32_t a_dst[2][AU], b_dst[2][BU];
    const float* a_src[AU];
    const float* b_src[BU];
    #pragma unroll
    for (int i = 0; i < AU; i++) {
        const int u = t + i * THREADS, r = u >> 3, c = u & 7;
        a_src[i] = A + (size_t)(bm + r) * GKD + c * 4;
        #pragma unroll
        for (int bf = 0; bf < 2; bf++)
            a_dst[bf][i] = smem_u32(&Asb[(bf * BM + r) * GBK + (c ^ (r & 7)) * 4]);
    }
    #pragma unroll
    for (int i = 0; i < BU; i++) {
        const int u = t + i * THREADS, r = u >> 3, c = u & 7;
        b_src[i] = W + (size_t)(bn + r) * GKD + c * 4;
        #pragma unroll
        for (int bf = 0; bf < 2; bf++)
            b_dst[bf][i] = smem_u32(&Bsb[(bf * GBN + r) * GBK + (c ^ (r & 7)) * 4]);
    }

    #pragma unroll
    for (int i = 0; i < AU; i++) cp16(a_dst[0][i], a_src[i]);
    #pragma unroll
    for (int i = 0; i < BU; i++) cp16(b_dst[0][i], b_src[i]);
    CP_COMMIT();

    float acc[2][6][4] = {};

    #pragma unroll
    for (int kc = 0; kc < NCHUNK; kc++) {
        const int buf = kc & 1;
        if (kc + 1 < NCHUNK) {
            const int ko = (kc + 1) * GBK;
            const int nb = (kc + 1) & 1;
            #pragma unroll
            for (int i = 0; i < AU; i++) cp16(a_dst[nb][i], a_src[i] + ko);
            #pragma unroll
            for (int i = 0; i < BU; i++) cp16(b_dst[nb][i], b_src[i] + ko);
            CP_COMMIT();
            CP_WAIT(1);
        } else {
            CP_WAIT(0);
        }
        __syncthreads();

        const uint32_t* Asl = Asb + buf * BM * GBK;
        const uint32_t* Bsl = Bsb + buf * GBN * GBK;

        #pragma unroll
        for (int k8 = 0; k8 < GBK / 8; k8++) {
            const int w0 = ((k8 * 2) ^ g) * 4 + q4;
            const int w1 = ((k8 * 2 + 1) ^ g) * 4 + q4;
            uint32_t a[2][4], b[6][2];
            #pragma unroll
            for (int mt = 0; mt < 2; mt++) {
                const int r = wM * 32 + mt * 16 + g;
                a[mt][0] = Asl[r * GBK + w0];
                a[mt][1] = Asl[(r + 8) * GBK + w0];
                a[mt][2] = Asl[r * GBK + w1];
                a[mt][3] = Asl[(r + 8) * GBK + w1];
            }
            #pragma unroll
            for (int nt = 0; nt < 6; nt++) {
                const int r = wN * 48 + nt * 8 + g;
                b[nt][0] = Bsl[r * GBK + w0];
                b[nt][1] = Bsl[r * GBK + w1];
            }
            #pragma unroll
            for (int mt = 0; mt < 2; mt++)
                #pragma unroll
                for (int nt = 0; nt < 6; nt++)
                    mma_tf32(acc[mt][nt], a[mt], b[nt]);
        }
        __syncthreads();
    }

    const float qs = 0.17677669529663687f;
    #pragma unroll
    for (int mt = 0; mt < 2; mt++) {
        const int row0 = bm + wM * 32 + mt * 16 + g;
        #pragma unroll
        for (int nt = 0; nt < 6; nt++) {
            const int col = bn + wN * 48 + nt * 8 + q4 * 2;
            const float sc = (scaleQ && col < CC) ? qs : 1.0f;
            float2 lo = make_float2(acc[mt][nt][0] * sc, acc[mt][nt][1] * sc);
            float2 hi = make_float2(acc[mt][nt][2] * sc, acc[mt][nt][3] * sc);
            *(float2*)(C + (size_t)row0 * Ncols + col) = lo;
            *(float2*)(C + (size_t)(row0 + 8) * Ncols + col) = hi;
        }
    }
}

// ---------------------------------------------------------------------------
// Tiled neighborhood attention, fp16 K/V in smem (unchanged from R7).
// ---------------------------------------------------------------------------
#define TILE_H 4
#define TILE_W 32
#define NRR (TILE_H + KW - 1)     // 10
#define NCC (TILE_W + KW - 1)     // 38
#define NNEI (NRR * NCC)          // 380
#define SROWH 40
#define SM_BYTES (2 * NNEI * SROWH * 2 + RR * RR * 4)

__global__ __launch_bounds__(128)
void natten2(const float* __restrict__ rpb, const float* __restrict__ temp)
{
    extern __shared__ char smraw[];
    __half* sKh  = (__half*)smraw;
    __half* sVh  = sKh + NNEI * SROWH;
    float*  srpb = (float*)(sVh + NNEI * SROWH);

    const int t      = threadIdx.x;
    const int tile   = blockIdx.x;
    const int bI     = blockIdx.y;
    const int head   = blockIdx.z;
    const int tile_i = (tile >> 1) * TILE_H;
    const int tile_j = (tile & 1) * TILE_W;
    const int ti0 = min(max(tile_i - 3, 0), HH - NRR);
    const int tj0 = min(max(tile_j - 3, 0), WW - NCC);
    const int pixbase = bI * HH * WW;

    const float tn = temp[head];
    for (int idx = t; idx < RR * RR; idx += 128)
        srpb[idx] = rpb[head * RR * RR + idx] * tn;

    for (int idx = t; idx < NNEI * 8; idx += 128) {
        const int d4 = idx & 7, r = idx >> 3;
        const int gi = ti0 + r / NCC, gj = tj0 + r % NCC;
        const float* base =
            g_qkv + (size_t)(pixbase + gi * WW + gj) * (3 * CC) + CC + head * HD;
        const float4 kk = *(const float4*)(base + d4 * 4);
        const float4 vv = *(const float4*)(base + CC + d4 * 4);
        __half* kp = sKh + r * SROWH + d4 * 4;
        __half* vp = sVh + r * SROWH + d4 * 4;
        *(__half2*)(kp)     = __floats2half2_rn(kk.x, kk.y);
        *(__half2*)(kp + 2) = __floats2half2_rn(kk.z, kk.w);
        *(__half2*)(vp)     = __floats2half2_rn(vv.x, vv.y);
        *(__half2*)(vp + 2) = __floats2half2_rn(vv.z, vv.w);
    }

    const int i  = tile_i + (t >> 5);
    const int j  = tile_j + (t & 31);
    const int pix = pixbase + i * WW + j;
    __half2 qh[16];
    {
        const float4* qp = (const float4*)(g_qkv + (size_t)pix * (3 * CC) + head * HD);
        #pragma unroll
        for (int d4 = 0; d4 < 8; d4++) {
            const float4 v = qp[d4];
            qh[d4 * 2]     = __floats2half2_rn(v.x * tn, v.y * tn);
            qh[d4 * 2 + 1] = __floats2half2_rn(v.z * tn, v.w * tn);
        }
    }
    __syncthreads();

    const int si = min(max(i - 3, 0), HH - KW);
    const int sj = min(max(j - 3, 0), WW - KW);
    const int lr0 = si - ti0, lc0 = sj - tj0;
    const int ri0 = si - i + 6, rj0 = sj - j + 6;

    float s[49];
    #pragma unroll
    for (int a = 0; a < 7; a++)
        #pragma unroll
        for (int c = 0; c < 7; c++)
            s[a * 7 + c] = srpb[(ri0 + a) * RR + rj0 + c];

    #pragma unroll
    for (int a = 0; a < 7; a++) {
        const __half* kb = sKh + ((lr0 + a) * NCC + lc0) * SROWH;
        #pragma unroll
        for (int c = 0; c < 7; c++) {
            const uint4* kr = (const uint4*)(kb + c * SROWH);
            __half2 acc = __float2half2_rn(0.f);
            #pragma unroll
            for (int ch = 0; ch < 4; ch++) {
                const uint4 kv = kr[ch];
                acc = __hfma2(qh[ch * 4 + 0], *(const __half2*)&kv.x, acc);
                acc = __hfma2(qh[ch * 4 + 1], *(const __half2*)&kv.y, acc);
                acc = __hfma2(qh[ch * 4 + 2], *(const __half2*)&kv.z, acc);
                acc = __hfma2(qh[ch * 4 + 3], *(const __half2*)&kv.w, acc);
            }
            const float2 f = __half22float2(acc);
            s[a * 7 + c] += f.x + f.y;
        }
    }

    float mx = s[0];
    #pragma unroll
    for (int n = 1; n < 49; n++) mx = fmaxf(mx, s[n]);
    float l = 0.f;
    #pragma unroll
    for (int n = 0; n < 49; n++) { s[n] = __expf(s[n] - mx); l += s[n]; }
    const float inv = 1.f / l;

    float o[32];
    #pragma unroll
    for (int d = 0; d < 32; d++) o[d] = 0.f;
    #pragma unroll
    for (int a = 0; a < 7; a++) {
        const __half* vb = sVh + ((lr0 + a) * NCC + lc0) * SROWH;
        #pragma unroll
        for (int c = 0; c < 7; c++) {
            const uint4* vr = (const uint4*)(vb + c * SROWH);
            const float w = s[a * 7 + c];
            #pragma unroll
            for (int ch = 0; ch < 4; ch++) {
                const uint4 vv = vr[ch];
                const float2 p0 = __half22float2(*(const __half2*)&vv.x);
                const float2 p1 = __half22float2(*(const __half2*)&vv.y);
                const float2 p2 = __half22float2(*(const __half2*)&vv.z);
                const float2 p3 = __half22float2(*(const __half2*)&vv.w);
                o[ch * 8 + 0] += w * p0.x; o[ch * 8 + 1] += w * p0.y;
                o[ch * 8 + 2] += w * p1.x; o[ch * 8 + 3] += w * p1.y;
                o[ch * 8 + 4] += w * p2.x; o[ch * 8 + 5] += w * p2.y;
                o[ch * 8 + 6] += w * p3.x; o[ch * 8 + 7] += w * p3.y;
            }
        }
    }

    float4* op = (float4*)(g_att + (size_t)pix * CC + head * HD);
    #pragma unroll
    for (int d4 = 0; d4 < 8; d4++) {
        float4 ov;
        ov.x = __uint_as_float(f2tf32(o[d4 * 4 + 0] * inv));
        ov.y = __uint_as_float(f2tf32(o[d4 * 4 + 1] * inv));
        ov.z = __uint_as_float(f2tf32(o[d4 * 4 + 2] * inv));
        ov.w = __uint_as_float(f2tf32(o[d4 * 4 + 3] * inv));
        op[d4] = ov;
    }
}

// ---------------------------------------------------------------------------
extern "C" void kernel_launch(void* const* d_in, const int* in_sizes, int n_in,
                              void* d_out, int out_size)
{
    const float* x      = (const float*)d_in[0];
    const float* w_qkv  = (const float*)d_in[1];
    const float* rpb    = (const float*)d_in[2];
    const float* temp   = (const float*)d_in[3];
    const float* w_proj = (const float*)d_in[4];
    float* out = (float*)d_out;

    void *qkvp, *attp, *xrp, *wqp, *wpp;
    cudaGetSymbolAddress(&qkvp, g_qkv);
    cudaGetSymbolAddress(&attp, g_att);
    cudaGetSymbolAddress(&xrp,  g_xr);
    cudaGetSymbolAddress(&wqp,  g_wqr);
    cudaGetSymbolAddress(&wpp,  g_wpr);

    const int smQ = 2 * (128 + GBN) * GBK * 4;   // 80 KB
    const int smP = 2 * (64 + GBN) * GBK * 4;    // 64 KB
    cudaFuncSetAttribute(gemm_mma<128, 512>,
                         cudaFuncAttributeMaxDynamicSharedMemorySize, smQ);
    cudaFuncSetAttribute(gemm_mma<64, 256>,
                         cudaFuncAttributeMaxDynamicSharedMemorySize, smP);
    cudaFuncSetAttribute(natten2, cudaFuncAttributeMaxDynamicSharedMemorySize,
                         SM_BYTES);

    // 0) tf32 rounding pre-pass
    round_pass<<<(N4TOT + 255) / 256, 256>>>(x, w_qkv, w_proj);

    // 1) QKV projection: [8192,192] x [576,192]^T -> g_qkv (q pre-scaled)
    gemm_mma<128, 512><<<dim3(3, NPIX / 128), 512, smQ>>>(
        (const float*)xrp, (const float*)wqp, (float*)qkvp, 3 * CC, 1);

    // 2) tiled neighborhood attention -> g_att (tf32-rounded)
    natten2<<<dim3(32, BBATCH, NH), 128, SM_BYTES>>>(rpb, temp);

    // 3) output projection: [8192,192] x [192,192]^T -> out
    gemm_mma<64, 256><<<dim3(1, NPIX / 64), 256, smP>>>(
        (const float*)attp, (const float*)wpp, out, CC, 0);
}

// round 9
// speedup vs baseline: 1.0783x; 1.0783x over previous
#include <cuda_runtime.h>
#include <cuda_fp16.h>
#include <cstdint>

#define BBATCH 2
#define HH 64
#define WW 64
#define CC 192
#define NH 6
#define HD 32
#define KW 7
#define RR 13
#define NPIX (BBATCH*HH*WW)

// scratch (device globals: allocation-free)
__device__ float g_qkv[(size_t)NPIX * 3 * CC];
__device__ float g_att[(size_t)NPIX * CC];
__device__ float g_xr [(size_t)NPIX * CC];
__device__ float g_wqr[(size_t)3 * CC * CC];
__device__ float g_wpr[(size_t)CC * CC];

__device__ __forceinline__ uint32_t f2tf32(float x) {
    uint32_t r;
    asm("cvt.rna.tf32.f32 %0, %1;" : "=r"(r) : "f"(x));
    return r;
}

__device__ __forceinline__ uint32_t smem_u32(const void* p) {
    uint32_t a;
    asm("{ .reg .u64 t; cvta.to.shared.u64 t, %1; cvt.u32.u64 %0, t; }"
        : "=r"(a) : "l"(p));
    return a;
}

__device__ __forceinline__ void cp16(uint32_t dst, const void* src) {
    asm volatile("cp.async.cg.shared.global [%0], [%1], 16;"
                 :: "r"(dst), "l"(src));
}
#define CP_COMMIT() asm volatile("cp.async.commit_group;" ::: "memory")
template<int N> __device__ __forceinline__ void cp_wait() {
    asm volatile("cp.async.wait_group %0;" :: "n"(N) : "memory");
}

__device__ __forceinline__ void mma_tf32(float c[4], const uint32_t a[4],
                                         const uint32_t b[2]) {
    asm volatile(
        "mma.sync.aligned.m16n8k8.row.col.f32.tf32.tf32.f32 "
        "{%0,%1,%2,%3}, {%4,%5,%6,%7}, {%8,%9}, {%0,%1,%2,%3};"
        : "+f"(c[0]), "+f"(c[1]), "+f"(c[2]), "+f"(c[3])
        : "r"(a[0]), "r"(a[1]), "r"(a[2]), "r"(a[3]), "r"(b[0]), "r"(b[1]));
}

// ---------------------------------------------------------------------------
// Pre-pass: round three fp32 arrays to tf32-representable fp32.
// ---------------------------------------------------------------------------
#define N4X ((NPIX * CC) / 4)
#define N4Q ((3 * CC * CC) / 4)
#define N4P ((CC * CC) / 4)
#define N4TOT (N4X + N4Q + N4P)

__global__ __launch_bounds__(256)
void round_pass(const float* __restrict__ x, const float* __restrict__ wq,
                const float* __restrict__ wp)
{
    const int idx = blockIdx.x * 256 + threadIdx.x;
    if (idx >= N4TOT) return;
    const float4* src;
    float4* dst;
    int off;
    if (idx < N4X)            { src = (const float4*)x;  dst = (float4*)g_xr;  off = idx; }
    else if (idx < N4X + N4Q) { src = (const float4*)wq; dst = (float4*)g_wqr; off = idx - N4X; }
    else                      { src = (const float4*)wp; dst = (float4*)g_wpr; off = idx - N4X - N4Q; }
    const float4 v = src[off];
    float4 o;
    o.x = __uint_as_float(f2tf32(v.x));
    o.y = __uint_as_float(f2tf32(v.y));
    o.z = __uint_as_float(f2tf32(v.z));
    o.w = __uint_as_float(f2tf32(v.w));
    dst[off] = o;
}

// ---------------------------------------------------------------------------
// Tensor-core GEMM via mma.sync tf32, 3-stage cp.async pipeline, BN=192.
// C[M,N] = A[M,192] * W[N,192]^T, NT, inputs pre-rounded to tf32.
// Warps: (BM/32) x 4; warp tile 32 x 48 (2 x 6 m16n8k8 chains).
// QKV: BM=128, 512 thr, grid (3,64). Proj: BM=64, 256 thr (2 CTAs/SM),
// grid (1,128). Ring of 3 smem buffers; wait_group keeps <=2 loads pending.
// ---------------------------------------------------------------------------
#define GBN 192
#define GBK 32
#define GKD 192
#define NCHUNK (GKD / GBK)     // 6
#define NSTAGE 3

template<int BM, int THREADS>
__global__ void __launch_bounds__(THREADS, (BM == 64) ? 2 : 1)
gemm_mma(const float* __restrict__ A, const float* __restrict__ W,
         float* __restrict__ C, int Ncols, int scaleQ)
{
    constexpr int AU = BM * 8 / THREADS;
    constexpr int BU = GBN * 8 / THREADS;

    extern __shared__ uint32_t smw[];
    uint32_t* Asb = smw;                         // [3][BM][32]
    uint32_t* Bsb = smw + NSTAGE * BM * GBK;     // [3][192][32]

    const int t    = threadIdx.x;
    const int wid  = t >> 5, lane = t & 31;
    const int g    = lane >> 2, q4 = lane & 3;
    const int wM   = wid >> 2, wN = wid & 3;
    const int bm   = blockIdx.y * BM;
    const int bn   = blockIdx.x * GBN;

    uint32_t a_dst[NSTAGE][AU], b_dst[NSTAGE][BU];
    const float* a_src[AU];
    const float* b_src[BU];
    #pragma unroll
    for (int i = 0; i < AU; i++) {
        const int u = t + i * THREADS, r = u >> 3, c = u & 7;
        a_src[i] = A + (size_t)(bm + r) * GKD + c * 4;
        #pragma unroll
        for (int bf = 0; bf < NSTAGE; bf++)
            a_dst[bf][i] = smem_u32(&Asb[(bf * BM + r) * GBK + (c ^ (r & 7)) * 4]);
    }
    #pragma unroll
    for (int i = 0; i < BU; i++) {
        const int u = t + i * THREADS, r = u >> 3, c = u & 7;
        b_src[i] = W + (size_t)(bn + r) * GKD + c * 4;
        #pragma unroll
        for (int bf = 0; bf < NSTAGE; bf++)
            b_dst[bf][i] = smem_u32(&Bsb[(bf * GBN + r) * GBK + (c ^ (r & 7)) * 4]);
    }

    // prologue: issue chunks 0..2 into bufs 0..2
    #pragma unroll
    for (int s = 0; s < NSTAGE; s++) {
        const int ko = s * GBK;
        #pragma unroll
        for (int i = 0; i < AU; i++) cp16(a_dst[s][i], a_src[i] + ko);
        #pragma unroll
        for (int i = 0; i < BU; i++) cp16(b_dst[s][i], b_src[i] + ko);
        CP_COMMIT();
    }

    float acc[2][6][4] = {};

    #pragma unroll
    for (int kc = 0; kc < NCHUNK; kc++) {
        const int buf = kc % NSTAGE;
        // chunk kc must be complete: pending groups allowed = issued-(kc+1)
        if (kc <= 3) cp_wait<2>();
        else if (kc == 4) cp_wait<1>();
        else cp_wait<0>();
        __syncthreads();

        const uint32_t* Asl = Asb + buf * BM * GBK;
        const uint32_t* Bsl = Bsb + buf * GBN * GBK;

        #pragma unroll
        for (int k8 = 0; k8 < GBK / 8; k8++) {
            const int w0 = ((k8 * 2) ^ g) * 4 + q4;
            const int w1 = ((k8 * 2 + 1) ^ g) * 4 + q4;
            uint32_t a[2][4], b[6][2];
            #pragma unroll
            for (int mt = 0; mt < 2; mt++) {
                const int r = wM * 32 + mt * 16 + g;
                a[mt][0] = Asl[r * GBK + w0];
                a[mt][1] = Asl[(r + 8) * GBK + w0];
                a[mt][2] = Asl[r * GBK + w1];
                a[mt][3] = Asl[(r + 8) * GBK + w1];
            }
            #pragma unroll
            for (int nt = 0; nt < 6; nt++) {
                const int r = wN * 48 + nt * 8 + g;
                b[nt][0] = Bsl[r * GBK + w0];
                b[nt][1] = Bsl[r * GBK + w1];
            }
            #pragma unroll
            for (int mt = 0; mt < 2; mt++)
                #pragma unroll
                for (int nt = 0; nt < 6; nt++)
                    mma_tf32(acc[mt][nt], a[mt], b[nt]);
        }
        __syncthreads();

        if (kc + NSTAGE < NCHUNK) {
            const int ko = (kc + NSTAGE) * GBK;
            #pragma unroll
            for (int i = 0; i < AU; i++) cp16(a_dst[buf][i], a_src[i] + ko);
            #pragma unroll
            for (int i = 0; i < BU; i++) cp16(b_dst[buf][i], b_src[i] + ko);
            CP_COMMIT();
        }
    }

    const float qs = 0.17677669529663687f;
    #pragma unroll
    for (int mt = 0; mt < 2; mt++) {
        const int row0 = bm + wM * 32 + mt * 16 + g;
        #pragma unroll
        for (int nt = 0; nt < 6; nt++) {
            const int col = bn + wN * 48 + nt * 8 + q4 * 2;
            const float sc = (scaleQ && col < CC) ? qs : 1.0f;
            float2 lo = make_float2(acc[mt][nt][0] * sc, acc[mt][nt][1] * sc);
            float2 hi = make_float2(acc[mt][nt][2] * sc, acc[mt][nt][3] * sc);
            *(float2*)(C + (size_t)row0 * Ncols + col) = lo;
            *(float2*)(C + (size_t)(row0 + 8) * Ncols + col) = hi;
        }
    }
}

// ---------------------------------------------------------------------------
// Tiled neighborhood attention, fp16 K/V in smem.
// AV: row-wise half2 accumulation (HFMA2), fp32 spill once per KW-row —
// cuts the fma-pipe op count from ~64 to ~23 per neighbor.
// ---------------------------------------------------------------------------
#define TILE_H 4
#define TILE_W 32
#define NRR (TILE_H + KW - 1)     // 10
#define NCC (TILE_W + KW - 1)     // 38
#define NNEI (NRR * NCC)          // 380
#define SROWH 40
#define SM_BYTES (2 * NNEI * SROWH * 2 + RR * RR * 4)

__global__ __launch_bounds__(128)
void natten2(const float* __restrict__ rpb, const float* __restrict__ temp)
{
    extern __shared__ char smraw[];
    __half* sKh  = (__half*)smraw;
    __half* sVh  = sKh + NNEI * SROWH;
    float*  srpb = (float*)(sVh + NNEI * SROWH);

    const int t      = threadIdx.x;
    const int tile   = blockIdx.x;
    const int bI     = blockIdx.y;
    const int head   = blockIdx.z;
    const int tile_i = (tile >> 1) * TILE_H;
    const int tile_j = (tile & 1) * TILE_W;
    const int ti0 = min(max(tile_i - 3, 0), HH - NRR);
    const int tj0 = min(max(tile_j - 3, 0), WW - NCC);
    const int pixbase = bI * HH * WW;

    const float tn = temp[head];
    for (int idx = t; idx < RR * RR; idx += 128)
        srpb[idx] = rpb[head * RR * RR + idx] * tn;

    for (int idx = t; idx < NNEI * 8; idx += 128) {
        const int d4 = idx & 7, r = idx >> 3;
        const int gi = ti0 + r / NCC, gj = tj0 + r % NCC;
        const float* base =
            g_qkv + (size_t)(pixbase + gi * WW + gj) * (3 * CC) + CC + head * HD;
        const float4 kk = *(const float4*)(base + d4 * 4);
        const float4 vv = *(const float4*)(base + CC + d4 * 4);
        __half* kp = sKh + r * SROWH + d4 * 4;
        __half* vp = sVh + r * SROWH + d4 * 4;
        *(__half2*)(kp)     = __floats2half2_rn(kk.x, kk.y);
        *(__half2*)(kp + 2) = __floats2half2_rn(kk.z, kk.w);
        *(__half2*)(vp)     = __floats2half2_rn(vv.x, vv.y);
        *(__half2*)(vp + 2) = __floats2half2_rn(vv.z, vv.w);
    }

    const int i  = tile_i + (t >> 5);
    const int j  = tile_j + (t & 31);
    const int pix = pixbase + i * WW + j;
    __half2 qh[16];
    {
        const float4* qp = (const float4*)(g_qkv + (size_t)pix * (3 * CC) + head * HD);
        #pragma unroll
        for (int d4 = 0; d4 < 8; d4++) {
            const float4 v = qp[d4];
            qh[d4 * 2]     = __floats2half2_rn(v.x * tn, v.y * tn);
            qh[d4 * 2 + 1] = __floats2half2_rn(v.z * tn, v.w * tn);
        }
    }
    __syncthreads();

    const int si = min(max(i - 3, 0), HH - KW);
    const int sj = min(max(j - 3, 0), WW - KW);
    const int lr0 = si - ti0, lc0 = sj - tj0;
    const int ri0 = si - i + 6, rj0 = sj - j + 6;

    float s[49];
    #pragma unroll
    for (int a = 0; a < 7; a++)
        #pragma unroll
        for (int c = 0; c < 7; c++)
            s[a * 7 + c] = srpb[(ri0 + a) * RR + rj0 + c];

    #pragma unroll
    for (int a = 0; a < 7; a++) {
        const __half* kb = sKh + ((lr0 + a) * NCC + lc0) * SROWH;
        #pragma unroll
        for (int c = 0; c < 7; c++) {
            const uint4* kr = (const uint4*)(kb + c * SROWH);
            __half2 acc = __float2half2_rn(0.f);
            #pragma unroll
            for (int ch = 0; ch < 4; ch++) {
                const uint4 kv = kr[ch];
                acc = __hfma2(qh[ch * 4 + 0], *(const __half2*)&kv.x, acc);
                acc = __hfma2(qh[ch * 4 + 1], *(const __half2*)&kv.y, acc);
                acc = __hfma2(qh[ch * 4 + 2], *(const __half2*)&kv.z, acc);
                acc = __hfma2(qh[ch * 4 + 3], *(const __half2*)&kv.w, acc);
            }
            const float2 f = __half22float2(acc);
            s[a * 7 + c] += f.x + f.y;
        }
    }

    float mx = s[0];
    #pragma unroll
    for (int n = 1; n < 49; n++) mx = fmaxf(mx, s[n]);
    float l = 0.f;
    #pragma unroll
    for (int n = 0; n < 49; n++) { s[n] = __expf(s[n] - mx); l += s[n]; }
    const float inv = 1.f / l;

    // AV: half2 accumulate within each KW-row, fp32 spill per row
    float o[32];
    #pragma unroll
    for (int d = 0; d < 32; d++) o[d] = 0.f;
    #pragma unroll
    for (int a = 0; a < 7; a++) {
        const __half* vb = sVh + ((lr0 + a) * NCC + lc0) * SROWH;
        __half2 oh[16];
        #pragma unroll
        for (int k = 0; k < 16; k++) oh[k] = __float2half2_rn(0.f);
        #pragma unroll
        for (int c = 0; c < 7; c++) {
            const uint4* vr = (const uint4*)(vb + c * SROWH);
            const __half2 w2 = __float2half2_rn(s[a * 7 + c]);
            #pragma unroll
            for (int ch = 0; ch < 4; ch++) {
                const uint4 vv = vr[ch];
                oh[ch * 4 + 0] = __hfma2(w2, *(const __half2*)&vv.x, oh[ch * 4 + 0]);
                oh[ch * 4 + 1] = __hfma2(w2, *(const __half2*)&vv.y, oh[ch * 4 + 1]);
                oh[ch * 4 + 2] = __hfma2(w2, *(const __half2*)&vv.z, oh[ch * 4 + 2]);
                oh[ch * 4 + 3] = __hfma2(w2, *(const __half2*)&vv.w, oh[ch * 4 + 3]);
            }
        }
        #pragma unroll
        for (int k = 0; k < 16; k++) {
            const float2 f = __half22float2(oh[k]);
            o[k * 2] += f.x; o[k * 2 + 1] += f.y;
        }
    }

    float4* op = (float4*)(g_att + (size_t)pix * CC + head * HD);
    #pragma unroll
    for (int d4 = 0; d4 < 8; d4++) {
        float4 ov;
        ov.x = __uint_as_float(f2tf32(o[d4 * 4 + 0] * inv));
        ov.y = __uint_as_float(f2tf32(o[d4 * 4 + 1] * inv));
        ov.z = __uint_as_float(f2tf32(o[d4 * 4 + 2] * inv));
        ov.w = __uint_as_float(f2tf32(o[d4 * 4 + 3] * inv));
        op[d4] = ov;
    }
}

// ---------------------------------------------------------------------------
extern "C" void kernel_launch(void* const* d_in, const int* in_sizes, int n_in,
                              void* d_out, int out_size)
{
    const float* x      = (const float*)d_in[0];
    const float* w_qkv  = (const float*)d_in[1];
    const float* rpb    = (const float*)d_in[2];
    const float* temp   = (const float*)d_in[3];
    const float* w_proj = (const float*)d_in[4];
    float* out = (float*)d_out;

    void *qkvp, *attp, *xrp, *wqp, *wpp;
    cudaGetSymbolAddress(&qkvp, g_qkv);
    cudaGetSymbolAddress(&attp, g_att);
    cudaGetSymbolAddress(&xrp,  g_xr);
    cudaGetSymbolAddress(&wqp,  g_wqr);
    cudaGetSymbolAddress(&wpp,  g_wpr);

    const int smQ = NSTAGE * (128 + GBN) * GBK * 4;   // 120 KB
    const int smP = NSTAGE * (64 + GBN) * GBK * 4;    // 96 KB
    cudaFuncSetAttribute(gemm_mma<128, 512>,
                         cudaFuncAttributeMaxDynamicSharedMemorySize, smQ);
    cudaFuncSetAttribute(gemm_mma<64, 256>,
                         cudaFuncAttributeMaxDynamicSharedMemorySize, smP);
    cudaFuncSetAttribute(natten2, cudaFuncAttributeMaxDynamicSharedMemorySize,
                         SM_BYTES);

    // 0) tf32 rounding pre-pass
    round_pass<<<(N4TOT + 255) / 256, 256>>>(x, w_qkv, w_proj);

    // 1) QKV projection: [8192,192] x [576,192]^T -> g_qkv (q pre-scaled)
    gemm_mma<128, 512><<<dim3(3, NPIX / 128), 512, smQ>>>(
        (const float*)xrp, (const float*)wqp, (float*)qkvp, 3 * CC, 1);

    // 2) tiled neighborhood attention -> g_att (tf32-rounded)
    natten2<<<dim3(32, BBATCH, NH), 128, SM_BYTES>>>(rpb, temp);

    // 3) output projection: [8192,192] x [192,192]^T -> out
    gemm_mma<64, 256><<<dim3(1, NPIX / 64), 256, smP>>>(
        (const float*)attp, (const float*)wpp, out, CC, 0);
}

// round 10
// speedup vs baseline: 1.2411x; 1.1511x over previous
#include <cuda_runtime.h>
#include <cuda_fp16.h>
#include <cstdint>

#define BBATCH 2
#define HH 64
#define WW 64
#define CC 192
#define NH 6
#define HD 32
#define KW 7
#define RR 13
#define NPIX (BBATCH*HH*WW)

// scratch (device globals: allocation-free) — all fp16
__device__ __half g_xh  [(size_t)NPIX * CC];
__device__ __half g_wqh [(size_t)3 * CC * CC];
__device__ __half g_wph [(size_t)CC * CC];
__device__ __half g_qkvh[(size_t)NPIX * 3 * CC];
__device__ __half g_atth[(size_t)NPIX * CC];

__device__ __forceinline__ uint32_t smem_u32(const void* p) {
    uint32_t a;
    asm("{ .reg .u64 t; cvta.to.shared.u64 t, %1; cvt.u32.u64 %0, t; }"
        : "=r"(a) : "l"(p));
    return a;
}
__device__ __forceinline__ void cp16(uint32_t dst, const void* src) {
    asm volatile("cp.async.cg.shared.global [%0], [%1], 16;"
                 :: "r"(dst), "l"(src));
}
#define CP_COMMIT() asm volatile("cp.async.commit_group;" ::: "memory")
template<int N> __device__ __forceinline__ void cp_wait() {
    asm volatile("cp.async.wait_group %0;" :: "n"(N) : "memory");
}

__device__ __forceinline__ void mma_f16(float c[4], const uint32_t a[4],
                                        const uint32_t b[2]) {
    asm volatile(
        "mma.sync.aligned.m16n8k16.row.col.f32.f16.f16.f32 "
        "{%0,%1,%2,%3}, {%4,%5,%6,%7}, {%8,%9}, {%0,%1,%2,%3};"
        : "+f"(c[0]), "+f"(c[1]), "+f"(c[2]), "+f"(c[3])
        : "r"(a[0]), "r"(a[1]), "r"(a[2]), "r"(a[3]), "r"(b[0]), "r"(b[1]));
}

// ---------------------------------------------------------------------------
// Pre-pass: convert x, w_qkv, w_proj fp32 -> fp16.
// ---------------------------------------------------------------------------
#define N4X ((NPIX * CC) / 4)
#define N4Q ((3 * CC * CC) / 4)
#define N4P ((CC * CC) / 4)
#define N4TOT (N4X + N4Q + N4P)

__global__ __launch_bounds__(256)
void cvt_pass(const float* __restrict__ x, const float* __restrict__ wq,
              const float* __restrict__ wp)
{
    const int idx = blockIdx.x * 256 + threadIdx.x;
    if (idx >= N4TOT) return;
    const float4* src;
    __half* dst;
    int off;
    if (idx < N4X)            { src = (const float4*)x;  dst = g_xh;  off = idx; }
    else if (idx < N4X + N4Q) { src = (const float4*)wq; dst = g_wqh; off = idx - N4X; }
    else                      { src = (const float4*)wp; dst = g_wph; off = idx - N4X - N4Q; }
    const float4 v = src[off];
    __half2* d2 = (__half2*)(dst + (size_t)off * 4);
    d2[0] = __floats2half2_rn(v.x, v.y);
    d2[1] = __floats2half2_rn(v.z, v.w);
}

// ---------------------------------------------------------------------------
// fp16 GEMM via mma.sync m16n8k16 (fp32 accum), 2-stage cp.async.
// C[M,N] = A[M,192] * W[N,192]^T, A/W fp16, row-major NT.
// K-chunk 64 halfs (128B/row); rows stored as 8x16B units with XOR swizzle
// (unit' = u ^ (r&7)) — staging and fragment LDS both conflict-free
// (all fragment rows == g (mod 8)).
// QKV: BM64 BN192 256thr (2x4 warps, warp 32x48) -> half out (q scaled).
// Proj: BM64 BN64 128thr (2x2 warps, warp 32x32) -> fp32 out.
// ---------------------------------------------------------------------------
#define GKD 192
#define GBKH 64                 // chunk: 64 halfs
#define NCH (GKD / GBKH)        // 3

template<int BM, int BN, int THREADS, int WN, int MINB, bool HALF_OUT>
__global__ void __launch_bounds__(THREADS, MINB)
gemm_h(const __half* __restrict__ A, const __half* __restrict__ W,
       void* __restrict__ Cout, int Ncols, int scaleQ)
{
    constexpr int NT = BN / WN / 8;          // n mma-tiles per warp
    constexpr int AU = BM * 8 / THREADS;     // A 16B-units per thread
    constexpr int BU = BN * 8 / THREADS;     // B 16B-units per thread

    extern __shared__ uint32_t smw[];
    uint32_t* Asb = smw;                     // [2][BM][32 words]
    uint32_t* Bsb = smw + 2 * BM * 32;       // [2][BN][32 words]

    const int t    = threadIdx.x;
    const int wid  = t >> 5, lane = t & 31;
    const int g    = lane >> 2, q4 = lane & 3;
    const int wM   = wid / WN, wN = wid % WN;
    const int bm   = blockIdx.y * BM;
    const int bn   = blockIdx.x * BN;

    uint32_t a_dst[2][AU], b_dst[2][BU];
    const __half* a_src[AU];
    const __half* b_src[BU];
    #pragma unroll
    for (int i = 0; i < AU; i++) {
        const int u = t + i * THREADS, r = u >> 3, c = u & 7;
        a_src[i] = A + (size_t)(bm + r) * GKD + c * 8;
        #pragma unroll
        for (int bf = 0; bf < 2; bf++)
            a_dst[bf][i] = smem_u32(&Asb[(bf * BM + r) * 32 + (c ^ (r & 7)) * 4]);
    }
    #pragma unroll
    for (int i = 0; i < BU; i++) {
        const int u = t + i * THREADS, r = u >> 3, c = u & 7;
        b_src[i] = W + (size_t)(bn + r) * GKD + c * 8;
        #pragma unroll
        for (int bf = 0; bf < 2; bf++)
            b_dst[bf][i] = smem_u32(&Bsb[(bf * BN + r) * 32 + (c ^ (r & 7)) * 4]);
    }

    // prologue: chunks 0,1 -> bufs 0,1
    #pragma unroll
    for (int s = 0; s < 2; s++) {
        #pragma unroll
        for (int i = 0; i < AU; i++) cp16(a_dst[s][i], a_src[i] + s * GBKH);
        #pragma unroll
        for (int i = 0; i < BU; i++) cp16(b_dst[s][i], b_src[i] + s * GBKH);
        CP_COMMIT();
    }

    float acc[2][NT][4] = {};

    #pragma unroll
    for (int kc = 0; kc < NCH; kc++) {
        const int buf = kc & 1;
        if (kc == NCH - 1) cp_wait<0>(); else cp_wait<1>();
        __syncthreads();

        const uint32_t* Asl = Asb + buf * BM * 32;
        const uint32_t* Bsl = Bsb + buf * BN * 32;

        #pragma unroll
        for (int kb = 0; kb < 4; kb++) {          // 4 k16 steps per chunk
            const int w0 = ((2 * kb) ^ g) * 4 + q4;
            const int w1 = ((2 * kb + 1) ^ g) * 4 + q4;
            uint32_t a[2][4], b[NT][2];
            #pragma unroll
            for (int mt = 0; mt < 2; mt++) {
                const int r = wM * 32 + mt * 16 + g;
                a[mt][0] = Asl[r * 32 + w0];
                a[mt][1] = Asl[(r + 8) * 32 + w0];
                a[mt][2] = Asl[r * 32 + w1];
                a[mt][3] = Asl[(r + 8) * 32 + w1];
            }
            #pragma unroll
            for (int nt = 0; nt < NT; nt++) {
                const int r = wN * (8 * NT) + nt * 8 + g;
                b[nt][0] = Bsl[r * 32 + w0];
                b[nt][1] = Bsl[r * 32 + w1];
            }
            #pragma unroll
            for (int mt = 0; mt < 2; mt++)
                #pragma unroll
                for (int nt = 0; nt < NT; nt++)
                    mma_f16(acc[mt][nt], a[mt], b[nt]);
        }
        __syncthreads();

        if (kc + 2 < NCH) {
            const int ko = (kc + 2) * GBKH;
            #pragma unroll
            for (int i = 0; i < AU; i++) cp16(a_dst[buf][i], a_src[i] + ko);
            #pragma unroll
            for (int i = 0; i < BU; i++) cp16(b_dst[buf][i], b_src[i] + ko);
            CP_COMMIT();
        }
    }

    const float qs = 0.17677669529663687f;
    #pragma unroll
    for (int mt = 0; mt < 2; mt++) {
        const int row0 = bm + wM * 32 + mt * 16 + g;
        #pragma unroll
        for (int nt = 0; nt < NT; nt++) {
            const int col = bn + wN * (8 * NT) + nt * 8 + q4 * 2;
            const float sc = (scaleQ && col < CC) ? qs : 1.0f;
            if (HALF_OUT) {
                __half* C = (__half*)Cout;
                *(__half2*)(C + (size_t)row0 * Ncols + col) =
                    __floats2half2_rn(acc[mt][nt][0] * sc, acc[mt][nt][1] * sc);
                *(__half2*)(C + (size_t)(row0 + 8) * Ncols + col) =
                    __floats2half2_rn(acc[mt][nt][2] * sc, acc[mt][nt][3] * sc);
            } else {
                float* C = (float*)Cout;
                *(float2*)(C + (size_t)row0 * Ncols + col) =
                    make_float2(acc[mt][nt][0] * sc, acc[mt][nt][1] * sc);
                *(float2*)(C + (size_t)(row0 + 8) * Ncols + col) =
                    make_float2(acc[mt][nt][2] * sc, acc[mt][nt][3] * sc);
            }
        }
    }
}

// ---------------------------------------------------------------------------
// Tiled neighborhood attention, all-fp16 I/O.
// K/V staged as raw 16B copies (no conversion); output stored fp16.
// ---------------------------------------------------------------------------
#define TILE_H 4
#define TILE_W 32
#define NRR (TILE_H + KW - 1)     // 10
#define NCC (TILE_W + KW - 1)     // 38
#define NNEI (NRR * NCC)          // 380
#define SROWH 40
#define SM_BYTES (2 * NNEI * SROWH * 2 + RR * RR * 4)

__global__ __launch_bounds__(128)
void natten2(const float* __restrict__ rpb, const float* __restrict__ temp)
{
    extern __shared__ char smraw[];
    __half* sKh  = (__half*)smraw;
    __half* sVh  = sKh + NNEI * SROWH;
    float*  srpb = (float*)(sVh + NNEI * SROWH);

    const int t      = threadIdx.x;
    const int tile   = blockIdx.x;
    const int bI     = blockIdx.y;
    const int head   = blockIdx.z;
    const int tile_i = (tile >> 1) * TILE_H;
    const int tile_j = (tile & 1) * TILE_W;
    const int ti0 = min(max(tile_i - 3, 0), HH - NRR);
    const int tj0 = min(max(tile_j - 3, 0), WW - NCC);
    const int pixbase = bI * HH * WW;

    const float tn = temp[head];
    for (int idx = t; idx < RR * RR; idx += 128)
        srpb[idx] = rpb[head * RR * RR + idx] * tn;

    // stage K,V: raw 16B copies of half rows (4 units per 32-half row)
    for (int idx = t; idx < NNEI * 4; idx += 128) {
        const int u = idx & 3, r = idx >> 2;
        const int gi = ti0 + r / NCC, gj = tj0 + r % NCC;
        const __half* base =
            g_qkvh + (size_t)(pixbase + gi * WW + gj) * (3 * CC) + CC + head * HD;
        *(uint4*)(sKh + r * SROWH + u * 8) = *(const uint4*)(base + u * 8);
        *(uint4*)(sVh + r * SROWH + u * 8) = *(const uint4*)(base + CC + u * 8);
    }

    // q: half loads, apply temperature
    const int i  = tile_i + (t >> 5);
    const int j  = tile_j + (t & 31);
    const int pix = pixbase + i * WW + j;
    __half2 qh[16];
    {
        const __half2* qp = (const __half2*)(g_qkvh + (size_t)pix * (3 * CC) + head * HD);
        const __half2 tn2 = __float2half2_rn(tn);
        #pragma unroll
        for (int k = 0; k < 16; k++) qh[k] = __hmul2(qp[k], tn2);
    }
    __syncthreads();

    const int si = min(max(i - 3, 0), HH - KW);
    const int sj = min(max(j - 3, 0), WW - KW);
    const int lr0 = si - ti0, lc0 = sj - tj0;
    const int ri0 = si - i + 6, rj0 = sj - j + 6;

    float s[49];
    #pragma unroll
    for (int a = 0; a < 7; a++)
        #pragma unroll
        for (int c = 0; c < 7; c++)
            s[a * 7 + c] = srpb[(ri0 + a) * RR + rj0 + c];

    #pragma unroll
    for (int a = 0; a < 7; a++) {
        const __half* kb = sKh + ((lr0 + a) * NCC + lc0) * SROWH;
        #pragma unroll
        for (int c = 0; c < 7; c++) {
            const uint4* kr = (const uint4*)(kb + c * SROWH);
            __half2 acc = __float2half2_rn(0.f);
            #pragma unroll
            for (int ch = 0; ch < 4; ch++) {
                const uint4 kv = kr[ch];
                acc = __hfma2(qh[ch * 4 + 0], *(const __half2*)&kv.x, acc);
                acc = __hfma2(qh[ch * 4 + 1], *(const __half2*)&kv.y, acc);
                acc = __hfma2(qh[ch * 4 + 2], *(const __half2*)&kv.z, acc);
                acc = __hfma2(qh[ch * 4 + 3], *(const __half2*)&kv.w, acc);
            }
            const float2 f = __half22float2(acc);
            s[a * 7 + c] += f.x + f.y;
        }
    }

    float mx = s[0];
    #pragma unroll
    for (int n = 1; n < 49; n++) mx = fmaxf(mx, s[n]);
    float l = 0.f;
    #pragma unroll
    for (int n = 0; n < 49; n++) { s[n] = __expf(s[n] - mx); l += s[n]; }
    const float inv = 1.f / l;

    // AV: half2 accumulate per KW-row, fp32 spill per row
    float o[32];
    #pragma unroll
    for (int d = 0; d < 32; d++) o[d] = 0.f;
    #pragma unroll
    for (int a = 0; a < 7; a++) {
        const __half* vb = sVh + ((lr0 + a) * NCC + lc0) * SROWH;
        __half2 oh[16];
        #pragma unroll
        for (int k = 0; k < 16; k++) oh[k] = __float2half2_rn(0.f);
        #pragma unroll
        for (int c = 0; c < 7; c++) {
            const uint4* vr = (const uint4*)(vb + c * SROWH);
            const __half2 w2 = __float2half2_rn(s[a * 7 + c]);
            #pragma unroll
            for (int ch = 0; ch < 4; ch++) {
                const uint4 vv = vr[ch];
                oh[ch * 4 + 0] = __hfma2(w2, *(const __half2*)&vv.x, oh[ch * 4 + 0]);
                oh[ch * 4 + 1] = __hfma2(w2, *(const __half2*)&vv.y, oh[ch * 4 + 1]);
                oh[ch * 4 + 2] = __hfma2(w2, *(const __half2*)&vv.z, oh[ch * 4 + 2]);
                oh[ch * 4 + 3] = __hfma2(w2, *(const __half2*)&vv.w, oh[ch * 4 + 3]);
            }
        }
        #pragma unroll
        for (int k = 0; k < 16; k++) {
            const float2 f = __half22float2(oh[k]);
            o[k * 2] += f.x; o[k * 2 + 1] += f.y;
        }
    }

    // store fp16 (feeds proj GEMM)
    __half2* op = (__half2*)(g_atth + (size_t)pix * CC + head * HD);
    #pragma unroll
    for (int k = 0; k < 16; k++)
        op[k] = __floats2half2_rn(o[k * 2] * inv, o[k * 2 + 1] * inv);
}

// ---------------------------------------------------------------------------
extern "C" void kernel_launch(void* const* d_in, const int* in_sizes, int n_in,
                              void* d_out, int out_size)
{
    const float* x      = (const float*)d_in[0];
    const float* w_qkv  = (const float*)d_in[1];
    const float* rpb    = (const float*)d_in[2];
    const float* temp   = (const float*)d_in[3];
    const float* w_proj = (const float*)d_in[4];
    float* out = (float*)d_out;

    void *xh, *wqh, *wph, *qkvh, *atth;
    cudaGetSymbolAddress(&xh,   g_xh);
    cudaGetSymbolAddress(&wqh,  g_wqh);
    cudaGetSymbolAddress(&wph,  g_wph);
    cudaGetSymbolAddress(&qkvh, g_qkvh);
    cudaGetSymbolAddress(&atth, g_atth);

    const int smQ = 2 * (64 + 192) * 32 * 4;   // 64 KB
    const int smP = 2 * (64 + 64) * 32 * 4;    // 32 KB
    cudaFuncSetAttribute((void*)gemm_h<64, 192, 256, 4, 2, true>,
                         cudaFuncAttributeMaxDynamicSharedMemorySize, smQ);
    cudaFuncSetAttribute((void*)gemm_h<64, 64, 128, 2, 4, false>,
                         cudaFuncAttributeMaxDynamicSharedMemorySize, smP);
    cudaFuncSetAttribute(natten2, cudaFuncAttributeMaxDynamicSharedMemorySize,
                         SM_BYTES);

    // 0) fp32 -> fp16 conversion pre-pass
    cvt_pass<<<(N4TOT + 255) / 256, 256>>>(x, w_qkv, w_proj);

    // 1) QKV projection: [8192,192] x [576,192]^T -> g_qkvh (half, q scaled)
    gemm_h<64, 192, 256, 4, 2, true><<<dim3(3, NPIX / 64), 256, smQ>>>(
        (const __half*)xh, (const __half*)wqh, qkvh, 3 * CC, 1);

    // 2) tiled neighborhood attention -> g_atth (half)
    natten2<<<dim3(32, BBATCH, NH), 128, SM_BYTES>>>(rpb, temp);

    // 3) output projection: [8192,192] x [192,192]^T -> out (fp32)
    gemm_h<64, 64, 128, 2, 4, false><<<dim3(3, NPIX / 64), 128, smP>>>(
        (const __half*)atth, (const __half*)wph, out, CC, 0);
}